// round 2
// baseline (speedup 1.0000x reference)
#include <cuda_runtime.h>
#include <cstdint>

#define B_     64
#define T_     128
#define U_     512
#define G4_    2048          // 4*U
#define PATH_  8192
#define ROWS_  (T_ * B_)     // 8192

// ---------------- scratch (device globals; no allocation allowed) ----------------
__device__ float g_enc_in  [ROWS_ * U_];          // 16 MB
__device__ float g_ZxE     [ROWS_ * G4_];         // 64 MB
__device__ float g_dec_in  [ROWS_ * U_];          // 16 MB
__device__ float g_ZxD     [ROWS_ * G4_];         // 64 MB
__device__ float g_dec_outs[ROWS_ * U_];          // 16 MB
__device__ float g_H1      [ROWS_ * G4_];         // 64 MB
__device__ float g_hbuf[2][3][U_ * B_];           // h double buffer, [u][b] layout
__device__ float g_cbuf[3][U_ * B_];              // c in-place,      [u][b] layout
__device__ int   g_idx_enc[ROWS_];
__device__ int   g_idx_dec[ROWS_];

// ---------------- helpers ----------------
__global__ void zero_states_kernel() {
    int i = blockIdx.x * blockDim.x + threadIdx.x;
    if (i < U_ * B_) {
        #pragma unroll
        for (int l = 0; l < 3; l++) {
            g_cbuf[l][i]    = 0.f;
            g_hbuf[0][l][i] = 0.f;
            g_hbuf[1][l][i] = 0.f;
        }
    }
}

// Build row index for gathered GEMM rows: out[t*B + b] = raw[b*T + t].
// Auto-detect int64 vs int32 storage: if stored as little-endian int64 with
// non-negative values < 2^31, every odd 32-bit word of the first 16 elements is 0.
__global__ void build_rowidx_kernel(const int* __restrict__ raw, int* __restrict__ out) {
    __shared__ int s_is64;
    if (threadIdx.x == 0) {
        int all0 = 1;
        #pragma unroll
        for (int i = 0; i < 16; i++)
            if (raw[2 * i + 1] != 0) all0 = 0;
        s_is64 = all0;
    }
    __syncthreads();
    int i = blockIdx.x * blockDim.x + threadIdx.x;   // i = b*T + t
    if (i < ROWS_) {
        int b = i / T_, t = i % T_;
        long long v;
        if (s_is64) v = ((const long long*)raw)[i];
        else        v = raw[i];
        out[t * B_ + b] = (int)v;
    }
}

// ---------------- generic fp32 SGEMM: C[M,N] = op(gather(A) @ B [+bias]) ----------------
// 128x128 block tile, BK=8, 256 threads, 8x8 micro-tile.
// Requires M%128==0, N%128==0, K%8==0 (true for all our shapes).
template<bool GATHER, bool RELU, bool SCATTER>
__global__ __launch_bounds__(256)
void sgemm128(int M, int N, int K,
              const float* __restrict__ A, int lda,
              const int* __restrict__ rowidx,
              const float* __restrict__ Bm, int ldb,
              const float* __restrict__ bias,
              float* __restrict__ C)
{
    __shared__ float As[8][128];
    __shared__ float Bs[8][128];

    int tid = threadIdx.x;
    int tx = tid & 15;          // 0..15 (N micro)
    int ty = tid >> 4;          // 0..15 (M micro)
    int m0 = blockIdx.y * 128;
    int n0 = blockIdx.x * 128;

    // A load map: each thread one float4 along K
    int arow = tid >> 1;                 // 0..127
    int ak   = (tid & 1) * 4;            // 0 or 4
    int grow = m0 + arow;
    long long asrc = GATHER ? (long long)rowidx[grow] : (long long)grow;
    const float* Aptr = A + asrc * lda + ak;

    // B load map: each thread one float4 along N
    int bk = tid >> 5;                   // 0..7
    int bn = (tid & 31) * 4;             // 0..124
    const float* Bptr = Bm + (long long)bk * ldb + n0 + bn;

    float acc[8][8];
    #pragma unroll
    for (int i = 0; i < 8; i++)
        #pragma unroll
        for (int j = 0; j < 8; j++) acc[i][j] = 0.f;

    for (int k0 = 0; k0 < K; k0 += 8) {
        float4 av = *(const float4*)(Aptr + k0);
        float4 bv = *(const float4*)(Bptr + (long long)k0 * ldb);
        __syncthreads();
        As[ak + 0][arow] = av.x;
        As[ak + 1][arow] = av.y;
        As[ak + 2][arow] = av.z;
        As[ak + 3][arow] = av.w;
        *(float4*)&Bs[bk][bn] = bv;
        __syncthreads();
        #pragma unroll
        for (int kk = 0; kk < 8; kk++) {
            float a[8], b[8];
            *(float4*)&a[0] = *(const float4*)&As[kk][ty * 8];
            *(float4*)&a[4] = *(const float4*)&As[kk][ty * 8 + 4];
            *(float4*)&b[0] = *(const float4*)&Bs[kk][tx * 8];
            *(float4*)&b[4] = *(const float4*)&Bs[kk][tx * 8 + 4];
            #pragma unroll
            for (int i = 0; i < 8; i++)
                #pragma unroll
                for (int j = 0; j < 8; j++)
                    acc[i][j] += a[i] * b[j];
        }
    }

    // epilogue
    float bv[8];
    if (bias) {
        #pragma unroll
        for (int j = 0; j < 8; j++) bv[j] = bias[n0 + tx * 8 + j];
    } else {
        #pragma unroll
        for (int j = 0; j < 8; j++) bv[j] = 0.f;
    }

    #pragma unroll
    for (int i = 0; i < 8; i++) {
        int row = m0 + ty * 8 + i;
        float out[8];
        #pragma unroll
        for (int j = 0; j < 8; j++) {
            float v = acc[i][j] + bv[j];
            if (RELU) v = v > 0.f ? v : 0.f;
            out[j] = v;
        }
        long long base;
        if (SCATTER) {
            // row = t*B + b  ->  out[b][t][n]
            int t = row >> 6;            // /64
            int b = row & 63;
            base = ((long long)b * T_ + t) * (long long)N + n0 + tx * 8;
        } else {
            base = (long long)row * N + n0 + tx * 8;
        }
        *(float4*)&C[base]     = make_float4(out[0], out[1], out[2], out[3]);
        *(float4*)&C[base + 4] = make_float4(out[4], out[5], out[6], out[7]);
    }
}

// ---------------- fused LSTM step: z-GEMM + gates + state update ----------------
// block = 128 threads: 32 u-lanes x 4 gates. Each thread: 8 batches (acc[8]).
// grid = (16 u-blocks, 8 b-blocks) = 128 blocks.
// h / c live in [u][b] layout -> h loads are float4 broadcasts, W loads coalesced.
__device__ __forceinline__ float sigm(float x) { return 1.f / (1.f + expf(-x)); }

__device__ __forceinline__ void lstm_mm(float acc[8],
                                        const float* __restrict__ W,  // [512][2048]
                                        const float* __restrict__ hs, // [512][64] + b0
                                        int col)
{
    #pragma unroll 8
    for (int k = 0; k < U_; k++) {
        float w = W[k * G4_ + col];
        float4 h0 = *(const float4*)(hs + k * B_);
        float4 h1 = *(const float4*)(hs + k * B_ + 4);
        acc[0] += w * h0.x; acc[1] += w * h0.y; acc[2] += w * h0.z; acc[3] += w * h0.w;
        acc[4] += w * h1.x; acc[5] += w * h1.y; acc[6] += w * h1.z; acc[7] += w * h1.w;
    }
}

__global__ __launch_bounds__(128)
void lstm_step_kernel(const float* __restrict__ Zx,     // [64][2048] pre-offset to t, or null
                      const float* __restrict__ xin,    // [512][64] lower-layer h (cur), or null
                      const float* __restrict__ Wx,     // [512][2048], or null (layer 0)
                      const float* __restrict__ Wh,     // [512][2048]
                      const float* __restrict__ bias,   // [2048]
                      const float* __restrict__ h_prev, // [512][64]
                      float* __restrict__ c_state,      // [512][64] in/out
                      float* __restrict__ h_out,        // [512][64]
                      float* __restrict__ dec_out)      // [64][512] pre-offset to t, or null
{
    int tid  = threadIdx.x;
    int lane = tid & 31;        // u lane
    int gate = tid >> 5;        // 0..3
    int ub   = blockIdx.x;      // 0..15
    int b0   = blockIdx.y * 8;  // batch base
    int u    = ub * 32 + lane;
    int col  = gate * U_ + u;

    float acc[8];
    float binit = bias[col];
    if (Zx) {
        #pragma unroll
        for (int i = 0; i < 8; i++) acc[i] = binit + Zx[(b0 + i) * G4_ + col];
    } else {
        #pragma unroll
        for (int i = 0; i < 8; i++) acc[i] = binit;
    }

    if (Wx) lstm_mm(acc, Wx, xin + b0, col);
    lstm_mm(acc, Wh, h_prev + b0, col);

    __shared__ float sz[4][32][8];
    #pragma unroll
    for (int i = 0; i < 8; i++) sz[gate][lane][i] = acc[i];
    __syncthreads();

    // 256 cell updates, 128 threads -> 2 each
    #pragma unroll
    for (int r = 0; r < 2; r++) {
        int idx = tid + r * 128;        // 0..255
        int ul  = idx & 31;
        int bi  = idx >> 5;             // 0..7
        float zi = sz[0][ul][bi];
        float zf = sz[1][ul][bi];
        float zg = sz[2][ul][bi];
        float zo = sz[3][ul][bi];
        float ig = sigm(zi);
        float fg = sigm(zf);
        float gg = tanhf(zg);
        float og = sigm(zo);
        int uu  = ub * 32 + ul;
        int b   = b0 + bi;
        int off = uu * B_ + b;
        float c2 = fg * c_state[off] + ig * gg;
        float h2 = og * tanhf(c2);
        c_state[off] = c2;
        h_out[off]   = h2;
        if (dec_out) dec_out[b * U_ + uu] = h2;   // row (t*B+b), col uu
    }
}

// ---------------- launch ----------------
extern "C" void kernel_launch(void* const* d_in, const int* in_sizes, int n_in,
                              void* d_out, int out_size)
{
    const int*   in_inputs   = (const int*)  d_in[0];
    const int*   in_targets  = (const int*)  d_in[1];
    const float* input_embed = (const float*)d_in[2];
    const float* enc_Wd      = (const float*)d_in[3];
    const float* enc_bd      = (const float*)d_in[4];
    const float* enc_Wx      = (const float*)d_in[5];
    const float* enc_Wh      = (const float*)d_in[6];
    const float* enc_b       = (const float*)d_in[7];
    const float* dec_embed   = (const float*)d_in[8];
    const float* dec_Wd      = (const float*)d_in[9];
    const float* dec_bd      = (const float*)d_in[10];
    const float* dec_Wx      = (const float*)d_in[11];
    const float* dec_Wh      = (const float*)d_in[12];
    const float* dec_b       = (const float*)d_in[13];
    const float* out_W1      = (const float*)d_in[14];
    const float* out_b1      = (const float*)d_in[15];
    const float* out_W2      = (const float*)d_in[16];
    const float* out_b2      = (const float*)d_in[17];

    float *p_enc_in, *p_ZxE, *p_dec_in, *p_ZxD, *p_dec_outs, *p_H1, *p_h, *p_c;
    int *p_idxE, *p_idxD;
    cudaGetSymbolAddress((void**)&p_enc_in,   g_enc_in);
    cudaGetSymbolAddress((void**)&p_ZxE,      g_ZxE);
    cudaGetSymbolAddress((void**)&p_dec_in,   g_dec_in);
    cudaGetSymbolAddress((void**)&p_ZxD,      g_ZxD);
    cudaGetSymbolAddress((void**)&p_dec_outs, g_dec_outs);
    cudaGetSymbolAddress((void**)&p_H1,       g_H1);
    cudaGetSymbolAddress((void**)&p_h,        g_hbuf);
    cudaGetSymbolAddress((void**)&p_c,        g_cbuf);
    cudaGetSymbolAddress((void**)&p_idxE,     g_idx_enc);
    cudaGetSymbolAddress((void**)&p_idxD,     g_idx_dec);

    const int SB = U_ * B_;   // one [u][b] state slab
    auto Hbuf = [&](int buf, int l) { return p_h + (buf * 3 + l) * SB; };
    auto Cbuf = [&](int l)          { return p_c + l * SB; };

    zero_states_kernel<<<(SB + 255) / 256, 256>>>();
    build_rowidx_kernel<<<(ROWS_ + 255) / 256, 256>>>(in_inputs,  p_idxE);
    build_rowidx_kernel<<<(ROWS_ + 255) / 256, 256>>>(in_targets, p_idxD);

    // enc_in = relu(embed(inputs) @ enc_Wd + enc_bd)           [8192,512] K=64
    sgemm128<true, true, false><<<dim3(U_ / 128, ROWS_ / 128), 256>>>(
        ROWS_, U_, 64, input_embed, 64, p_idxE, enc_Wd, U_, enc_bd, p_enc_in);
    // ZxE = enc_in @ enc_Wx[0]                                 [8192,2048] K=512
    sgemm128<false, false, false><<<dim3(G4_ / 128, ROWS_ / 128), 256>>>(
        ROWS_, G4_, U_, p_enc_in, U_, nullptr, enc_Wx, G4_, nullptr, p_ZxE);
    // dec_in = relu(embed(targets) @ dec_Wd + dec_bd)          [8192,512] K=2048
    sgemm128<true, true, false><<<dim3(U_ / 128, ROWS_ / 128), 256>>>(
        ROWS_, U_, 2048, dec_embed, 2048, p_idxD, dec_Wd, U_, dec_bd, p_dec_in);
    // ZxD = dec_in @ dec_Wx[0]                                 [8192,2048] K=512
    sgemm128<false, false, false><<<dim3(G4_ / 128, ROWS_ / 128), 256>>>(
        ROWS_, G4_, U_, p_dec_in, U_, nullptr, dec_Wx, G4_, nullptr, p_ZxD);

    // -------- recurrence: 128 enc steps then 128 dec steps, 3 layers each --------
    const long long WSTRIDE = (long long)U_ * G4_;   // per-layer weight stride
    for (int s = 0; s < 256; s++) {
        bool enc = (s < 128);
        int  t   = enc ? s : s - 128;
        int  rb  = s & 1;
        int  wb  = rb ^ 1;
        const float* Wx_  = enc ? enc_Wx : dec_Wx;
        const float* Wh_  = enc ? enc_Wh : dec_Wh;
        const float* b_   = enc ? enc_b  : dec_b;
        const float* Zx_  = (enc ? p_ZxE : p_ZxD) + (long long)t * B_ * G4_;

        for (int l = 0; l < 3; l++) {
            float* dout = (!enc && l == 2) ? (p_dec_outs + (long long)t * B_ * U_) : nullptr;
            lstm_step_kernel<<<dim3(16, 8), 128>>>(
                (l == 0) ? Zx_ : nullptr,
                (l == 0) ? nullptr : Hbuf(wb, l - 1),
                (l == 0) ? nullptr : (Wx_ + l * WSTRIDE),
                Wh_ + l * WSTRIDE,
                b_ + l * G4_,
                Hbuf(rb, l),
                Cbuf(l),
                Hbuf(wb, l),
                dout);
        }
    }

    // -------- output head --------
    // H1 = relu(dec_outs @ out_W1 + out_b1)                    [8192,2048] K=512
    sgemm128<false, true, false><<<dim3(G4_ / 128, ROWS_ / 128), 256>>>(
        ROWS_, G4_, U_, p_dec_outs, U_, nullptr, out_W1, G4_, out_b1, p_H1);
    // out = relu(H1 @ out_W2 + out_b2), scattered to [B,T,PATH] [8192,8192] K=2048
    sgemm128<false, true, true><<<dim3(PATH_ / 128, ROWS_ / 128), 256>>>(
        ROWS_, PATH_, 2048, p_H1, 2048, nullptr, out_W2, PATH_, out_b2, (float*)d_out);
}

// round 6
// speedup vs baseline: 2.8605x; 2.8605x over previous
#include <cuda_runtime.h>
#include <cstdint>

#define B_     64
#define T_     128
#define U_     512
#define G4_    2048          // 4*U
#define PATH_  8192
#define ROWS_  (T_ * B_)     // 8192
#define NBLK   128           // persistent kernel grid (co-resident: <= 148 SMs)

// ---------------- scratch (device globals; no allocation allowed) ----------------
__device__ float g_enc_in  [ROWS_ * U_];
__device__ float g_ZxE     [ROWS_ * G4_];
__device__ float g_dec_in  [ROWS_ * U_];
__device__ float g_ZxD     [ROWS_ * G4_];
__device__ float g_dec_outs[ROWS_ * U_];
__device__ float g_H1      [ROWS_ * G4_];
__device__ float g_hbuf[2][3][U_ * B_];           // h double buffer, [u][b] layout
__device__ float g_cbuf[3][U_ * B_];              // c in-place,      [u][b] layout
__device__ float g_zpart[4 * G4_ * B_];           // K-split partials [kc][col][b]
__device__ int   g_idx_enc[ROWS_];
__device__ int   g_idx_dec[ROWS_];
__device__ unsigned int g_bar_count;
__device__ unsigned int g_bar_gen;

// ---------------- f32x2 packed-FMA helpers (sm_100+) ----------------
__device__ __forceinline__ unsigned long long pk2(float lo, float hi) {
    unsigned long long r;
    asm("mov.b64 %0, {%1, %2};" : "=l"(r) : "f"(lo), "f"(hi));
    return r;
}
__device__ __forceinline__ void upk2(unsigned long long v, float &lo, float &hi) {
    asm("mov.b64 {%0, %1}, %2;" : "=f"(lo), "=f"(hi) : "l"(v));
}
__device__ __forceinline__ void fma2(unsigned long long &d, unsigned long long a,
                                     unsigned long long b) {
    asm("fma.rn.f32x2 %0, %1, %2, %0;" : "+l"(d) : "l"(a), "l"(b));
}

__device__ __forceinline__ float sigm(float x) { return 1.f / (1.f + expf(-x)); }

// ---------------- helpers ----------------
__global__ void zero_states_kernel() {
    int i = blockIdx.x * blockDim.x + threadIdx.x;
    if (i == 0) { g_bar_count = 0u; g_bar_gen = 0u; }
    if (i < U_ * B_) {
        #pragma unroll
        for (int l = 0; l < 3; l++) {
            g_cbuf[l][i]    = 0.f;
            g_hbuf[0][l][i] = 0.f;
            g_hbuf[1][l][i] = 0.f;
        }
    }
}

// out[t*B + b] = raw[b*T + t]; auto-detect int64 vs int32 storage.
__global__ void build_rowidx_kernel(const int* __restrict__ raw, int* __restrict__ out) {
    __shared__ int s_is64;
    if (threadIdx.x == 0) {
        int all0 = 1;
        #pragma unroll
        for (int i = 0; i < 16; i++)
            if (raw[2 * i + 1] != 0) all0 = 0;
        s_is64 = all0;
    }
    __syncthreads();
    int i = blockIdx.x * blockDim.x + threadIdx.x;   // i = b*T + t
    if (i < ROWS_) {
        int b = i / T_, t = i % T_;
        long long v;
        if (s_is64) v = ((const long long*)raw)[i];
        else        v = raw[i];
        out[t * B_ + b] = (int)v;
    }
}

// ---------------- fp32 SGEMM with FFMA2: C[M,N] = op(gather(A) @ B [+bias]) ----------------
// 128x128 block tile, BK=8, 256 threads, 8x8 micro-tile via f32x2 packed FMA.
template<bool GATHER, bool RELU, bool SCATTER>
__global__ __launch_bounds__(256)
void sgemm128(int M, int N, int K,
              const float* __restrict__ A, int lda,
              const int* __restrict__ rowidx,
              const float* __restrict__ Bm, int ldb,
              const float* __restrict__ bias,
              float* __restrict__ C)
{
    __shared__ __align__(16) float As2[8][256];   // A values duplicated in pairs
    __shared__ __align__(16) float Bs[8][128];

    int tid = threadIdx.x;
    int tx = tid & 15;          // N micro
    int ty = tid >> 4;          // M micro
    int m0 = blockIdx.y * 128;
    int n0 = blockIdx.x * 128;

    // A load map: each thread one float4 along K
    int arow = tid >> 1;                 // 0..127
    int ak   = (tid & 1) * 4;            // 0 or 4
    int grow = m0 + arow;
    long long asrc = GATHER ? (long long)rowidx[grow] : (long long)grow;
    const float* Aptr = A + asrc * lda + ak;

    // B load map: each thread one float4 along N
    int bk = tid >> 5;                   // 0..7
    int bn = (tid & 31) * 4;             // 0..124
    const float* Bptr = Bm + (long long)bk * ldb + n0 + bn;

    unsigned long long acc[8][4];
    #pragma unroll
    for (int i = 0; i < 8; i++)
        #pragma unroll
        for (int j = 0; j < 4; j++) acc[i][j] = 0ULL;

    float4 av = *(const float4*)(Aptr);
    float4 bv = *(const float4*)(Bptr);

    for (int k0 = 0; k0 < K; k0 += 8) {
        __syncthreads();
        As2[ak + 0][2 * arow] = av.x;  As2[ak + 0][2 * arow + 1] = av.x;
        As2[ak + 1][2 * arow] = av.y;  As2[ak + 1][2 * arow + 1] = av.y;
        As2[ak + 2][2 * arow] = av.z;  As2[ak + 2][2 * arow + 1] = av.z;
        As2[ak + 3][2 * arow] = av.w;  As2[ak + 3][2 * arow + 1] = av.w;
        *(float4*)&Bs[bk][bn] = bv;
        __syncthreads();
        if (k0 + 8 < K) {               // prefetch next tile under the FMA block
            av = *(const float4*)(Aptr + k0 + 8);
            bv = *(const float4*)(Bptr + (long long)(k0 + 8) * ldb);
        }
        #pragma unroll
        for (int kk = 0; kk < 8; kk++) {
            const ulonglong2* ap = (const ulonglong2*)&As2[kk][ty * 16];
            const ulonglong2* bp = (const ulonglong2*)&Bs[kk][tx * 8];
            ulonglong2 a01 = ap[0], a23 = ap[1], a45 = ap[2], a67 = ap[3];
            ulonglong2 b03 = bp[0], b47 = bp[1];
            unsigned long long ad[8] = {a01.x, a01.y, a23.x, a23.y,
                                        a45.x, a45.y, a67.x, a67.y};
            unsigned long long bd[4] = {b03.x, b03.y, b47.x, b47.y};
            #pragma unroll
            for (int i = 0; i < 8; i++) {
                fma2(acc[i][0], ad[i], bd[0]);
                fma2(acc[i][1], ad[i], bd[1]);
                fma2(acc[i][2], ad[i], bd[2]);
                fma2(acc[i][3], ad[i], bd[3]);
            }
        }
    }

    float bvv[8];
    if (bias) {
        #pragma unroll
        for (int j = 0; j < 8; j++) bvv[j] = bias[n0 + tx * 8 + j];
    } else {
        #pragma unroll
        for (int j = 0; j < 8; j++) bvv[j] = 0.f;
    }

    #pragma unroll
    for (int i = 0; i < 8; i++) {
        int row = m0 + ty * 8 + i;
        float out[8];
        #pragma unroll
        for (int jp = 0; jp < 4; jp++) upk2(acc[i][jp], out[2 * jp], out[2 * jp + 1]);
        #pragma unroll
        for (int j = 0; j < 8; j++) {
            float v = out[j] + bvv[j];
            if (RELU) v = v > 0.f ? v : 0.f;
            out[j] = v;
        }
        long long base;
        if (SCATTER) {
            int t = row >> 6;            // row = t*B + b
            int b = row & 63;
            base = ((long long)b * T_ + t) * (long long)N + n0 + tx * 8;
        } else {
            base = (long long)row * N + n0 + tx * 8;
        }
        *(float4*)&C[base]     = make_float4(out[0], out[1], out[2], out[3]);
        *(float4*)&C[base + 4] = make_float4(out[4], out[5], out[6], out[7]);
    }
}

// ---------------- software grid sync (all NBLK blocks co-resident) ----------------
__device__ __forceinline__ void grid_sync(unsigned int &gen) {
    __syncthreads();
    if (threadIdx.x == 0) {
        __threadfence();
        unsigned int old = atomicAdd(&g_bar_count, 1u);
        if (old == NBLK - 1) {
            g_bar_count = 0u;
            __threadfence();
            atomicAdd(&g_bar_gen, 1u);
        } else {
            while (*(volatile unsigned int*)&g_bar_gen == gen) __nanosleep(64);
        }
    }
    gen++;
    __syncthreads();
    __threadfence();
}

// ---------------- persistent LSTM recurrence: 256 steps x 3 layers, one launch ----
// Per layer: matvec phase (z = Wx^T x + Wh^T h, K-split into 4 chunks over 128
// blocks: 16 col-tiles x 2 batch-tiles x 4 K-chunks) -> grid sync ->
// gate phase (sum partials + bias + Zx, sigmoid/tanh, c/h update) -> grid sync.
__global__ __launch_bounds__(256)
void lstm_persistent(const float* __restrict__ enc_Wx, const float* __restrict__ enc_Wh,
                     const float* __restrict__ enc_b,
                     const float* __restrict__ dec_Wx, const float* __restrict__ dec_Wh,
                     const float* __restrict__ dec_b,
                     const float* __restrict__ ZxE, const float* __restrict__ ZxD,
                     float* __restrict__ dec_outs)
{
    __shared__ __align__(16) float s_h[256][32];
    int tid = threadIdx.x;
    int bid = blockIdx.x;
    unsigned int gen = 0;

    int ct = bid & 15;                  // col tile (128 cols each)
    int bt = (bid >> 4) & 1;            // batch tile (32 each)
    int kc = bid >> 5;                  // K chunk (0..3)
    int col = ct * 128 + (tid & 127);
    int bh  = tid >> 7;                 // batch half within tile (16 each)
    int b0  = bt * 32;

    // gate-phase cell for this thread: exactly one of 512u x 64b cells
    int gcell = bid * 256 + tid;        // 0..32767
    int gu = gcell >> 6;                // 0..511
    int gb = gcell & 63;                // 0..63

    const long long WSTRIDE = (long long)U_ * G4_;

    for (int s = 0; s < 256; s++) {
        bool enc = s < 128;
        int t  = enc ? s : s - 128;
        int rb = s & 1, wb = rb ^ 1;
        const float* Wx   = enc ? enc_Wx : dec_Wx;
        const float* Wh   = enc ? enc_Wh : dec_Wh;
        const float* bias = enc ? enc_b  : dec_b;
        const float* Zx   = (enc ? ZxE : ZxD) + (long long)t * B_ * G4_;

        for (int l = 0; l < 3; l++) {
            // ---- matvec phase ----
            int Kc, koff;
            const float* W;
            const float* src;
            if (l == 0) {
                Kc = 128; koff = kc * 128;
                W = Wh;                                  // layer-0 Wh
                src = &g_hbuf[rb][0][0];
            } else {
                Kc = 256; koff = (kc & 1) * 256;
                W = (kc < 2 ? Wx : Wh) + (long long)l * WSTRIDE;
                src = (kc < 2) ? &g_hbuf[wb][l - 1][0]   // x = lower layer h (this step)
                               : &g_hbuf[rb][l][0];      // h = own h (prev step)
            }

            // stage h/x chunk into smem (L2 reads: written by other SMs)
            int nf4 = Kc * 8;
            for (int i = tid; i < nf4; i += 256) {
                int kk = i >> 3, j = (i & 7) * 4;
                float4 v = __ldcg((const float4*)(src + (long long)(koff + kk) * B_ + b0 + j));
                *(float4*)&s_h[kk][j] = v;
            }
            __syncthreads();

            unsigned long long acc[8];
            #pragma unroll
            for (int p = 0; p < 8; p++) acc[p] = 0ULL;
            const float* Wp = W + (long long)koff * G4_ + col;
            #pragma unroll 4
            for (int kk = 0; kk < Kc; kk++) {
                float w = Wp[(long long)kk * G4_];
                unsigned long long w2 = pk2(w, w);
                const ulonglong2* hp = (const ulonglong2*)&s_h[kk][bh * 16];
                ulonglong2 q0 = hp[0], q1 = hp[1], q2 = hp[2], q3 = hp[3];
                fma2(acc[0], w2, q0.x); fma2(acc[1], w2, q0.y);
                fma2(acc[2], w2, q1.x); fma2(acc[3], w2, q1.y);
                fma2(acc[4], w2, q2.x); fma2(acc[5], w2, q2.y);
                fma2(acc[6], w2, q3.x); fma2(acc[7], w2, q3.y);
            }
            float* zp = g_zpart + ((long long)kc * G4_ + col) * B_ + b0 + bh * 16;
            #pragma unroll
            for (int p = 0; p < 8; p++) {
                float lo, hi; upk2(acc[p], lo, hi);
                zp[2 * p] = lo; zp[2 * p + 1] = hi;
            }
            grid_sync(gen);

            // ---- gate phase: 512u x 64b cells, exactly one per thread ----
            {
                float* c_st = &g_cbuf[l][0];
                float* h_o  = &g_hbuf[wb][l][0];
                float zv[4];
                #pragma unroll
                for (int g = 0; g < 4; g++) {
                    int cc = g * U_ + gu;                // z column 0..2047
                    float ssum = bias[l * G4_ + cc];
                    #pragma unroll
                    for (int k2 = 0; k2 < 4; k2++)
                        ssum += __ldcg(&g_zpart[((long long)k2 * G4_ + cc) * B_ + gb]);
                    if (l == 0) ssum += Zx[(long long)gb * G4_ + cc];
                    zv[g] = ssum;
                }
                float ig = sigm(zv[0]), fg = sigm(zv[1]);
                float gg = tanhf(zv[2]), og = sigm(zv[3]);
                int off = gu * B_ + gb;
                float c2 = fg * c_st[off] + ig * gg;     // same thread wrote it last step
                float h2 = og * tanhf(c2);
                c_st[off] = c2;
                h_o[off]  = h2;
                if (!enc && l == 2)
                    dec_outs[((long long)t * B_ + gb) * U_ + gu] = h2;
            }
            grid_sync(gen);
        }
    }
}

// ---------------- launch ----------------
extern "C" void kernel_launch(void* const* d_in, const int* in_sizes, int n_in,
                              void* d_out, int out_size)
{
    const int*   in_inputs   = (const int*)  d_in[0];
    const int*   in_targets  = (const int*)  d_in[1];
    const float* input_embed = (const float*)d_in[2];
    const float* enc_Wd      = (const float*)d_in[3];
    const float* enc_bd      = (const float*)d_in[4];
    const float* enc_Wx      = (const float*)d_in[5];
    const float* enc_Wh      = (const float*)d_in[6];
    const float* enc_b       = (const float*)d_in[7];
    const float* dec_embed   = (const float*)d_in[8];
    const float* dec_Wd      = (const float*)d_in[9];
    const float* dec_bd      = (const float*)d_in[10];
    const float* dec_Wx      = (const float*)d_in[11];
    const float* dec_Wh      = (const float*)d_in[12];
    const float* dec_b       = (const float*)d_in[13];
    const float* out_W1      = (const float*)d_in[14];
    const float* out_b1      = (const float*)d_in[15];
    const float* out_W2      = (const float*)d_in[16];
    const float* out_b2      = (const float*)d_in[17];

    float *p_enc_in, *p_ZxE, *p_dec_in, *p_ZxD, *p_dec_outs, *p_H1;
    int *p_idxE, *p_idxD;
    cudaGetSymbolAddress((void**)&p_enc_in,   g_enc_in);
    cudaGetSymbolAddress((void**)&p_ZxE,      g_ZxE);
    cudaGetSymbolAddress((void**)&p_dec_in,   g_dec_in);
    cudaGetSymbolAddress((void**)&p_ZxD,      g_ZxD);
    cudaGetSymbolAddress((void**)&p_dec_outs, g_dec_outs);
    cudaGetSymbolAddress((void**)&p_H1,       g_H1);
    cudaGetSymbolAddress((void**)&p_idxE,     g_idx_enc);
    cudaGetSymbolAddress((void**)&p_idxD,     g_idx_dec);

    zero_states_kernel<<<(U_ * B_ + 255) / 256, 256>>>();
    build_rowidx_kernel<<<(ROWS_ + 255) / 256, 256>>>(in_inputs,  p_idxE);
    build_rowidx_kernel<<<(ROWS_ + 255) / 256, 256>>>(in_targets, p_idxD);

    // enc_in = relu(embed(inputs) @ enc_Wd + enc_bd)           [8192,512] K=64
    sgemm128<true, true, false><<<dim3(U_ / 128, ROWS_ / 128), 256>>>(
        ROWS_, U_, 64, input_embed, 64, p_idxE, enc_Wd, U_, enc_bd, p_enc_in);
    // ZxE = enc_in @ enc_Wx[0]                                 [8192,2048] K=512
    sgemm128<false, false, false><<<dim3(G4_ / 128, ROWS_ / 128), 256>>>(
        ROWS_, G4_, U_, p_enc_in, U_, nullptr, enc_Wx, G4_, nullptr, p_ZxE);
    // dec_in = relu(embed(targets) @ dec_Wd + dec_bd)          [8192,512] K=2048
    sgemm128<true, true, false><<<dim3(U_ / 128, ROWS_ / 128), 256>>>(
        ROWS_, U_, 2048, dec_embed, 2048, p_idxD, dec_Wd, U_, dec_bd, p_dec_in);
    // ZxD = dec_in @ dec_Wx[0]                                 [8192,2048] K=512
    sgemm128<false, false, false><<<dim3(G4_ / 128, ROWS_ / 128), 256>>>(
        ROWS_, G4_, U_, p_dec_in, U_, nullptr, dec_Wx, G4_, nullptr, p_ZxD);

    // -------- recurrence: one persistent launch --------
    lstm_persistent<<<NBLK, 256>>>(enc_Wx, enc_Wh, enc_b, dec_Wx, dec_Wh, dec_b,
                                   p_ZxE, p_ZxD, p_dec_outs);

    // -------- output head --------
    // H1 = relu(dec_outs @ out_W1 + out_b1)                    [8192,2048] K=512
    sgemm128<false, true, false><<<dim3(G4_ / 128, ROWS_ / 128), 256>>>(
        ROWS_, G4_, U_, p_dec_outs, U_, nullptr, out_W1, G4_, out_b1, p_H1);
    // out = relu(H1 @ out_W2 + out_b2), scattered to [B,T,PATH] [8192,8192] K=2048
    sgemm128<false, true, true><<<dim3(PATH_ / 128, ROWS_ / 128), 256>>>(
        ROWS_, PATH_, 2048, p_H1, 2048, nullptr, out_W2, PATH_, out_b2, (float*)d_out);
}

// round 9
// speedup vs baseline: 3.4093x; 1.1918x over previous
#include <cuda_runtime.h>
#include <cuda_bf16.h>
#include <cstdint>

#define B_     64
#define T_     128
#define U_     512
#define G4_    2048          // 4*U
#define PATH_  8192
#define ROWS_  (T_ * B_)     // 8192
#define NBLK   128           // persistent kernel grid

// ---------------- scratch (device globals; no allocation allowed) ----------------
__device__ float g_enc_in  [ROWS_ * U_];
__device__ float g_ZxE     [ROWS_ * G4_];
__device__ float g_ZxD     [ROWS_ * G4_];
__device__ float g_dec_outs[ROWS_ * U_];
__device__ float g_hbuf[2][3][U_ * B_];
__device__ float g_cbuf[3][U_ * B_];
__device__ float g_zpart[4 * G4_ * B_];
__device__ int   g_idx_enc[ROWS_];
__device__ int   g_idx_dec[ROWS_];
__device__ unsigned int g_bar_count;
__device__ unsigned int g_bar_gen;

// bf16 hi/lo planes (stored as ushort)
__device__ unsigned short g_ei_hi[ROWS_ * U_],   g_ei_lo[ROWS_ * U_];     // enc_in
__device__ unsigned short g_de_hi[PATH_ * 2048], g_de_lo[PATH_ * 2048];   // dec_embed table
__device__ unsigned short g_di_hi[ROWS_ * U_],   g_di_lo[ROWS_ * U_];     // dec_in
__device__ unsigned short g_do_hi[ROWS_ * U_],   g_do_lo[ROWS_ * U_];     // dec_outs
__device__ unsigned short g_h1_hi[ROWS_ * G4_],  g_h1_lo[ROWS_ * G4_];    // H1
__device__ unsigned short g_wxe_hi[G4_ * U_],    g_wxe_lo[G4_ * U_];      // enc_Wx0^T [2048][512]
__device__ unsigned short g_wxd_hi[G4_ * U_],    g_wxd_lo[G4_ * U_];      // dec_Wx0^T
__device__ unsigned short g_wd_hi [U_ * 2048],   g_wd_lo [U_ * 2048];     // dec_Wd^T  [512][2048]
__device__ unsigned short g_w1_hi [G4_ * U_],    g_w1_lo [G4_ * U_];      // out_W1^T  [2048][512]
__device__ unsigned short g_w2_hi [PATH_ * G4_], g_w2_lo [PATH_ * G4_];   // out_W2^T  [8192][2048]

// ---------------- helpers ----------------
__device__ __forceinline__ uint32_t smem_to_u32(const void* p) {
    uint32_t a;
    asm("{ .reg .u64 t; cvta.to.shared.u64 t, %1; cvt.u32.u64 %0, t; }" : "=r"(a) : "l"(p));
    return a;
}
__device__ __forceinline__ unsigned short bf16h(float x) {
    __nv_bfloat16 t = __float2bfloat16(x);
    return *reinterpret_cast<unsigned short*>(&t);
}
__device__ __forceinline__ float bf16f(unsigned short u) {
    __nv_bfloat16 t = *reinterpret_cast<__nv_bfloat16*>(&u);
    return __bfloat162float(t);
}
__device__ __forceinline__ float sigm(float x) { return 1.f / (1.f + expf(-x)); }

__device__ __forceinline__ unsigned long long pk2(float lo, float hi) {
    unsigned long long r;
    asm("mov.b64 %0, {%1, %2};" : "=l"(r) : "f"(lo), "f"(hi));
    return r;
}
__device__ __forceinline__ void upk2(unsigned long long v, float &lo, float &hi) {
    asm("mov.b64 {%0, %1}, %2;" : "=f"(lo), "=f"(hi) : "l"(v));
}
__device__ __forceinline__ void fma2(unsigned long long &d, unsigned long long a,
                                     unsigned long long b) {
    asm("fma.rn.f32x2 %0, %1, %2, %0;" : "+l"(d) : "l"(a), "l"(b));
}

// ldmatrix x4 (non-transposed)
__device__ __forceinline__ void ldm4(uint32_t r[4], uint32_t addr) {
    asm volatile("ldmatrix.sync.aligned.m8n8.x4.shared.b16 {%0,%1,%2,%3}, [%4];"
                 : "=r"(r[0]), "=r"(r[1]), "=r"(r[2]), "=r"(r[3]) : "r"(addr));
}
// bf16 mma: D += A*B
__device__ __forceinline__ void mma_bf16(float d[4], const uint32_t a[4], const uint32_t b[2]) {
    asm volatile("mma.sync.aligned.m16n8k16.row.col.f32.bf16.bf16.f32 "
                 "{%0,%1,%2,%3}, {%4,%5,%6,%7}, {%8,%9}, {%0,%1,%2,%3};"
                 : "+f"(d[0]), "+f"(d[1]), "+f"(d[2]), "+f"(d[3])
                 : "r"(a[0]), "r"(a[1]), "r"(a[2]), "r"(a[3]), "r"(b[0]), "r"(b[1]));
}

// ---------------- small kernels ----------------
__global__ void zero_states_kernel() {
    int i = blockIdx.x * blockDim.x + threadIdx.x;
    if (i == 0) { g_bar_count = 0u; g_bar_gen = 0u; }
    if (i < U_ * B_) {
        #pragma unroll
        for (int l = 0; l < 3; l++) {
            g_cbuf[l][i] = 0.f; g_hbuf[0][l][i] = 0.f; g_hbuf[1][l][i] = 0.f;
        }
    }
}

__global__ void build_rowidx_kernel(const int* __restrict__ raw, int* __restrict__ out) {
    __shared__ int s_is64;
    if (threadIdx.x == 0) {
        int all0 = 1;
        #pragma unroll
        for (int i = 0; i < 16; i++)
            if (raw[2 * i + 1] != 0) all0 = 0;
        s_is64 = all0;
    }
    __syncthreads();
    int i = blockIdx.x * blockDim.x + threadIdx.x;
    if (i < ROWS_) {
        int b = i / T_, t = i % T_;
        long long v = s_is64 ? ((const long long*)raw)[i] : (long long)raw[i];
        out[t * B_ + b] = (int)v;
    }
}

// fp32 -> bf16 hi/lo planes (same layout), vectorized
__global__ void convert_split_kernel(const float* __restrict__ src,
                                     unsigned short* __restrict__ hi,
                                     unsigned short* __restrict__ lo, long long n4) {
    long long i = (long long)blockIdx.x * blockDim.x + threadIdx.x;
    long long stride = (long long)gridDim.x * blockDim.x;
    for (; i < n4; i += stride) {
        float4 v = *(const float4*)(src + i * 4);
        unsigned short h0 = bf16h(v.x), h1 = bf16h(v.y), h2 = bf16h(v.z), h3 = bf16h(v.w);
        unsigned short l0 = bf16h(v.x - bf16f(h0)), l1 = bf16h(v.y - bf16f(h1));
        unsigned short l2 = bf16h(v.z - bf16f(h2)), l3 = bf16h(v.w - bf16f(h3));
        ((uint32_t*)hi)[i * 2]     = (uint32_t)h0 | ((uint32_t)h1 << 16);
        ((uint32_t*)hi)[i * 2 + 1] = (uint32_t)h2 | ((uint32_t)h3 << 16);
        ((uint32_t*)lo)[i * 2]     = (uint32_t)l0 | ((uint32_t)l1 << 16);
        ((uint32_t*)lo)[i * 2 + 1] = (uint32_t)l2 | ((uint32_t)l3 << 16);
    }
}

// fp32 [K][N] -> bf16 [N][K] hi/lo planes (transpose + split)
__global__ void convertBT_kernel(const float* __restrict__ src,
                                 unsigned short* __restrict__ hi,
                                 unsigned short* __restrict__ lo, int K, int N) {
    __shared__ float t[32][33];
    int k0 = blockIdx.y * 32, n0 = blockIdx.x * 32;
    int tx = threadIdx.x, ty = threadIdx.y;   // (32, 8)
    #pragma unroll
    for (int j = 0; j < 4; j++) {
        int kk = ty + j * 8;
        t[kk][tx] = src[(long long)(k0 + kk) * N + n0 + tx];
    }
    __syncthreads();
    #pragma unroll
    for (int j = 0; j < 4; j++) {
        int nn = ty + j * 8;
        float v = t[tx][nn];                  // = src[k0+tx][n0+nn]
        unsigned short h = bf16h(v);
        long long o = (long long)(n0 + nn) * K + k0 + tx;
        hi[o] = h;
        lo[o] = bf16h(v - bf16f(h));
    }
}

// ---------------- fp32 SGEMM (enc_in only: M=8192,N=512,K=64) ----------------
__global__ __launch_bounds__(256)
void sgemm_encin(const float* __restrict__ A, const int* __restrict__ rowidx,
                 const float* __restrict__ Bm, const float* __restrict__ bias,
                 float* __restrict__ C)
{
    const int K = 64, N = U_;
    __shared__ __align__(16) float As2[8][256];
    __shared__ __align__(16) float Bs[8][128];
    int tid = threadIdx.x;
    int tx = tid & 15, ty = tid >> 4;
    int m0 = blockIdx.y * 128, n0 = blockIdx.x * 128;
    int arow = tid >> 1, ak = (tid & 1) * 4;
    long long asrc = (long long)rowidx[m0 + arow];
    const float* Aptr = A + asrc * K + ak;
    int bk = tid >> 5, bn = (tid & 31) * 4;
    const float* Bptr = Bm + (long long)bk * N + n0 + bn;

    unsigned long long acc[8][4];
    #pragma unroll
    for (int i = 0; i < 8; i++)
        #pragma unroll
        for (int j = 0; j < 4; j++) acc[i][j] = 0ULL;

    float4 av = *(const float4*)(Aptr);
    float4 bv = *(const float4*)(Bptr);
    for (int k0 = 0; k0 < K; k0 += 8) {
        __syncthreads();
        As2[ak+0][2*arow] = av.x; As2[ak+0][2*arow+1] = av.x;
        As2[ak+1][2*arow] = av.y; As2[ak+1][2*arow+1] = av.y;
        As2[ak+2][2*arow] = av.z; As2[ak+2][2*arow+1] = av.z;
        As2[ak+3][2*arow] = av.w; As2[ak+3][2*arow+1] = av.w;
        *(float4*)&Bs[bk][bn] = bv;
        __syncthreads();
        if (k0 + 8 < K) {
            av = *(const float4*)(Aptr + k0 + 8);
            bv = *(const float4*)(Bptr + (long long)(k0 + 8) * N);
        }
        #pragma unroll
        for (int kk = 0; kk < 8; kk++) {
            const ulonglong2* ap = (const ulonglong2*)&As2[kk][ty * 16];
            const ulonglong2* bp = (const ulonglong2*)&Bs[kk][tx * 8];
            ulonglong2 a01 = ap[0], a23 = ap[1], a45 = ap[2], a67 = ap[3];
            ulonglong2 b03 = bp[0], b47 = bp[1];
            unsigned long long ad[8] = {a01.x, a01.y, a23.x, a23.y, a45.x, a45.y, a67.x, a67.y};
            unsigned long long bd[4] = {b03.x, b03.y, b47.x, b47.y};
            #pragma unroll
            for (int i = 0; i < 8; i++) {
                fma2(acc[i][0], ad[i], bd[0]); fma2(acc[i][1], ad[i], bd[1]);
                fma2(acc[i][2], ad[i], bd[2]); fma2(acc[i][3], ad[i], bd[3]);
            }
        }
    }
    float bvv[8];
    #pragma unroll
    for (int j = 0; j < 8; j++) bvv[j] = bias[n0 + tx * 8 + j];
    #pragma unroll
    for (int i = 0; i < 8; i++) {
        int row = m0 + ty * 8 + i;
        float out[8];
        #pragma unroll
        for (int jp = 0; jp < 4; jp++) upk2(acc[i][jp], out[2*jp], out[2*jp+1]);
        #pragma unroll
        for (int j = 0; j < 8; j++) {
            float v = out[j] + bvv[j];
            out[j] = v > 0.f ? v : 0.f;
        }
        long long base = (long long)row * N + n0 + tx * 8;
        *(float4*)&C[base]     = make_float4(out[0], out[1], out[2], out[3]);
        *(float4*)&C[base + 4] = make_float4(out[4], out[5], out[6], out[7]);
    }
}

// ---------------- HMMA bf16 split GEMM (mma.sync, base PTX -> works on sm_103) ------
// C[M,N] = op( (Ahi+Alo) @ (Bhi+Blo)^T ), dropping lo*lo.
// A planes [M][K] bf16 row-major; B planes [N][K] bf16 (= col-major for mma row.col).
// CTA 128x128, 8 warps as 4(M) x 2(N); warp tile 32x64 (2 m16 x 8 n8).
// K staged by 16 in smem, 48B row stride (conflict-free ldmatrix), reg prefetch.
template<bool GATHER, bool RELU, int OUTM>    // OUTM: 0=f32, 1=f32 scatter[B,T,N], 2=bf16 split
__global__ __launch_bounds__(256)
void mma_gemm(int M, int N, int K,
              const unsigned short* __restrict__ Ahi, const unsigned short* __restrict__ Alo,
              const int* __restrict__ rowidx,
              const unsigned short* __restrict__ Bhi, const unsigned short* __restrict__ Blo,
              const float* __restrict__ bias,
              float* __restrict__ C,
              unsigned short* __restrict__ Chi, unsigned short* __restrict__ Clo)
{
    // 4 planes of [128 rows][24 elems] bf16 (48B stride)
    __shared__ __align__(16) unsigned short sAh[128][24], sAl[128][24];
    __shared__ __align__(16) unsigned short sBh[128][24], sBl[128][24];

    int tid = threadIdx.x, lane = tid & 31, wid = tid >> 5;
    int wm = wid & 3, wn = wid >> 2;              // warp grid 4x2
    int m0 = blockIdx.y * 128, n0 = blockIdx.x * 128;

    // loader mapping: thread -> (row, 16B chunk)
    int lrow = tid >> 1, lch = tid & 1;
    long long aR = GATHER ? (long long)__ldg(rowidx + m0 + lrow) : (long long)(m0 + lrow);
    const unsigned short* pAh = Ahi + aR * K + lch * 8;
    const unsigned short* pAl = Alo + aR * K + lch * 8;
    const unsigned short* pBh = Bhi + (long long)(n0 + lrow) * K + lch * 8;
    const unsigned short* pBl = Blo + (long long)(n0 + lrow) * K + lch * 8;

    // ldmatrix smem addresses (byte offsets within a plane)
    uint32_t bAh = smem_to_u32(sAh), bAl = smem_to_u32(sAl);
    uint32_t bBh = smem_to_u32(sBh), bBl = smem_to_u32(sBl);
    int g = lane >> 3;
    // A x4: M0=m[0:8]k[0:8], M1=m[8:16]k[0:8], M2=m[0:8]k[8:16], M3=m[8:16]k[8:16]
    uint32_t aoff = (uint32_t)((wm * 32 + ((g & 1) << 3) + (lane & 7)) * 48 + (g >> 1) * 16);
    // B x4 (2 n-tiles): M0=n[0:8]k[0:8], M1=n[0:8]k[8:16], M2=n[8:16]k[0:8], M3=n[8:16]k[8:16]
    uint32_t boff = (uint32_t)((wn * 64 + ((g >> 1) << 3) + (lane & 7)) * 48 + (g & 1) * 16);
    uint32_t sst  = (uint32_t)(lrow * 48 + lch * 16);   // store offset

    float acc[2][8][4];
    #pragma unroll
    for (int i = 0; i < 2; i++)
        #pragma unroll
        for (int j = 0; j < 8; j++)
            #pragma unroll
            for (int v = 0; v < 4; v++) acc[i][j][v] = 0.f;

    uint4 va = *(const uint4*)pAh, vb = *(const uint4*)pAl;
    uint4 vc = *(const uint4*)pBh, vd = *(const uint4*)pBl;

    for (int k0 = 0; k0 < K; k0 += 16) {
        __syncthreads();
        *(uint4*)((char*)sAh + sst) = va;
        *(uint4*)((char*)sAl + sst) = vb;
        *(uint4*)((char*)sBh + sst) = vc;
        *(uint4*)((char*)sBl + sst) = vd;
        __syncthreads();
        if (k0 + 16 < K) {
            va = *(const uint4*)(pAh + k0 + 16);
            vb = *(const uint4*)(pAl + k0 + 16);
            vc = *(const uint4*)(pBh + k0 + 16);
            vd = *(const uint4*)(pBl + k0 + 16);
        }

        uint32_t ah[2][4], al[2][4], bh[8][2], bl[8][2];
        #pragma unroll
        for (int mt = 0; mt < 2; mt++) {
            ldm4(ah[mt], bAh + aoff + (uint32_t)(mt * 16 * 48));
            ldm4(al[mt], bAl + aoff + (uint32_t)(mt * 16 * 48));
        }
        #pragma unroll
        for (int pr = 0; pr < 4; pr++) {
            uint32_t r[4];
            ldm4(r, bBh + boff + (uint32_t)(pr * 16 * 48));
            bh[pr*2][0] = r[0]; bh[pr*2][1] = r[1]; bh[pr*2+1][0] = r[2]; bh[pr*2+1][1] = r[3];
            ldm4(r, bBl + boff + (uint32_t)(pr * 16 * 48));
            bl[pr*2][0] = r[0]; bl[pr*2][1] = r[1]; bl[pr*2+1][0] = r[2]; bl[pr*2+1][1] = r[3];
        }
        #pragma unroll
        for (int mt = 0; mt < 2; mt++)
            #pragma unroll
            for (int nt = 0; nt < 8; nt++) {
                mma_bf16(acc[mt][nt], ah[mt], bh[nt]);
                mma_bf16(acc[mt][nt], ah[mt], bl[nt]);
                mma_bf16(acc[mt][nt], al[mt], bh[nt]);
            }
    }

    // epilogue: thread t in warp holds rows (grp, grp+8), cols (lane&3)*2 +{0,1}
    int grp = lane >> 2, qc = (lane & 3) * 2;
    #pragma unroll
    for (int mt = 0; mt < 2; mt++) {
        #pragma unroll
        for (int nt = 0; nt < 8; nt++) {
            int c = n0 + wn * 64 + nt * 8 + qc;
            float b0 = bias ? __ldg(bias + c)     : 0.f;
            float b1 = bias ? __ldg(bias + c + 1) : 0.f;
            #pragma unroll
            for (int hr = 0; hr < 2; hr++) {
                int m = m0 + wm * 32 + mt * 16 + grp + hr * 8;
                float v0 = acc[mt][nt][hr * 2]     + b0;
                float v1 = acc[mt][nt][hr * 2 + 1] + b1;
                if (RELU) { v0 = v0 > 0.f ? v0 : 0.f; v1 = v1 > 0.f ? v1 : 0.f; }
                if (OUTM == 2) {
                    long long base = (long long)m * N + c;
                    unsigned short h0 = bf16h(v0), h1 = bf16h(v1);
                    unsigned short l0 = bf16h(v0 - bf16f(h0)), l1 = bf16h(v1 - bf16f(h1));
                    *(uint32_t*)(Chi + base) = (uint32_t)h0 | ((uint32_t)h1 << 16);
                    *(uint32_t*)(Clo + base) = (uint32_t)l0 | ((uint32_t)l1 << 16);
                } else {
                    long long base = (OUTM == 1)
                        ? ((long long)(m & 63) * T_ + (m >> 6)) * (long long)N + c
                        : (long long)m * N + c;
                    *(float2*)(C + base) = make_float2(v0, v1);
                }
            }
        }
    }
}

// ---------------- software grid sync ----------------
__device__ __forceinline__ void grid_sync(unsigned int &gen) {
    __syncthreads();
    if (threadIdx.x == 0) {
        __threadfence();
        unsigned int old = atomicAdd(&g_bar_count, 1u);
        if (old == NBLK - 1) {
            g_bar_count = 0u;
            __threadfence();
            atomicAdd(&g_bar_gen, 1u);
        } else {
            while (*(volatile unsigned int*)&g_bar_gen == gen) __nanosleep(64);
        }
    }
    gen++;
    __syncthreads();
    __threadfence();
}

// ---------------- persistent LSTM recurrence (unchanged) ----------------
__global__ __launch_bounds__(256)
void lstm_persistent(const float* __restrict__ enc_Wx, const float* __restrict__ enc_Wh,
                     const float* __restrict__ enc_b,
                     const float* __restrict__ dec_Wx, const float* __restrict__ dec_Wh,
                     const float* __restrict__ dec_b,
                     const float* __restrict__ ZxE, const float* __restrict__ ZxD,
                     float* __restrict__ dec_outs)
{
    __shared__ __align__(16) float s_h[256][32];
    int tid = threadIdx.x;
    int bid = blockIdx.x;
    unsigned int gen = 0;

    int ct = bid & 15;
    int bt = (bid >> 4) & 1;
    int kc = bid >> 5;
    int col = ct * 128 + (tid & 127);
    int bh  = tid >> 7;
    int b0  = bt * 32;

    int gcell = bid * 256 + tid;
    int gu = gcell >> 6;
    int gb = gcell & 63;

    const long long WSTRIDE = (long long)U_ * G4_;

    for (int s = 0; s < 256; s++) {
        bool enc = s < 128;
        int t  = enc ? s : s - 128;
        int rb = s & 1, wb = rb ^ 1;
        const float* Wx   = enc ? enc_Wx : dec_Wx;
        const float* Wh   = enc ? enc_Wh : dec_Wh;
        const float* bias = enc ? enc_b  : dec_b;
        const float* Zx   = (enc ? ZxE : ZxD) + (long long)t * B_ * G4_;

        for (int l = 0; l < 3; l++) {
            int Kc, koff;
            const float* W;
            const float* src;
            if (l == 0) {
                Kc = 128; koff = kc * 128;
                W = Wh;
                src = &g_hbuf[rb][0][0];
            } else {
                Kc = 256; koff = (kc & 1) * 256;
                W = (kc < 2 ? Wx : Wh) + (long long)l * WSTRIDE;
                src = (kc < 2) ? &g_hbuf[wb][l - 1][0] : &g_hbuf[rb][l][0];
            }

            int nf4 = Kc * 8;
            for (int i = tid; i < nf4; i += 256) {
                int kk = i >> 3, j = (i & 7) * 4;
                float4 vv = __ldcg((const float4*)(src + (long long)(koff + kk) * B_ + b0 + j));
                *(float4*)&s_h[kk][j] = vv;
            }
            __syncthreads();

            unsigned long long acc[8];
            #pragma unroll
            for (int p = 0; p < 8; p++) acc[p] = 0ULL;
            const float* Wp = W + (long long)koff * G4_ + col;
            #pragma unroll 4
            for (int kk = 0; kk < Kc; kk++) {
                float w = Wp[(long long)kk * G4_];
                unsigned long long w2 = pk2(w, w);
                const ulonglong2* hp = (const ulonglong2*)&s_h[kk][bh * 16];
                ulonglong2 q0 = hp[0], q1 = hp[1], q2 = hp[2], q3 = hp[3];
                fma2(acc[0], w2, q0.x); fma2(acc[1], w2, q0.y);
                fma2(acc[2], w2, q1.x); fma2(acc[3], w2, q1.y);
                fma2(acc[4], w2, q2.x); fma2(acc[5], w2, q2.y);
                fma2(acc[6], w2, q3.x); fma2(acc[7], w2, q3.y);
            }
            float* zp = g_zpart + ((long long)kc * G4_ + col) * B_ + b0 + bh * 16;
            #pragma unroll
            for (int p = 0; p < 8; p++) {
                float lo, hi; upk2(acc[p], lo, hi);
                zp[2 * p] = lo; zp[2 * p + 1] = hi;
            }
            grid_sync(gen);

            {
                float* c_st = &g_cbuf[l][0];
                float* h_o  = &g_hbuf[wb][l][0];
                float zv[4];
                #pragma unroll
                for (int gg2 = 0; gg2 < 4; gg2++) {
                    int cc = gg2 * U_ + gu;
                    float ssum = bias[l * G4_ + cc];
                    #pragma unroll
                    for (int k2 = 0; k2 < 4; k2++)
                        ssum += __ldcg(&g_zpart[((long long)k2 * G4_ + cc) * B_ + gb]);
                    if (l == 0) ssum += Zx[(long long)gb * G4_ + cc];
                    zv[gg2] = ssum;
                }
                float ig = sigm(zv[0]), fg = sigm(zv[1]);
                float gg = tanhf(zv[2]), og = sigm(zv[3]);
                int off = gu * B_ + gb;
                float c2 = fg * c_st[off] + ig * gg;
                float h2 = og * tanhf(c2);
                c_st[off] = c2;
                h_o[off]  = h2;
                if (!enc && l == 2)
                    dec_outs[((long long)t * B_ + gb) * U_ + gu] = h2;
            }
            grid_sync(gen);
        }
    }
}

// ---------------- launch ----------------
extern "C" void kernel_launch(void* const* d_in, const int* in_sizes, int n_in,
                              void* d_out, int out_size)
{
    const int*   in_inputs   = (const int*)  d_in[0];
    const int*   in_targets  = (const int*)  d_in[1];
    const float* input_embed = (const float*)d_in[2];
    const float* enc_Wd      = (const float*)d_in[3];
    const float* enc_bd      = (const float*)d_in[4];
    const float* enc_Wx      = (const float*)d_in[5];
    const float* enc_Wh      = (const float*)d_in[6];
    const float* enc_b       = (const float*)d_in[7];
    const float* dec_embed   = (const float*)d_in[8];
    const float* dec_Wd      = (const float*)d_in[9];
    const float* dec_bd      = (const float*)d_in[10];
    const float* dec_Wx      = (const float*)d_in[11];
    const float* dec_Wh      = (const float*)d_in[12];
    const float* dec_b       = (const float*)d_in[13];
    const float* out_W1      = (const float*)d_in[14];
    const float* out_b1      = (const float*)d_in[15];
    const float* out_W2      = (const float*)d_in[16];
    const float* out_b2      = (const float*)d_in[17];

    float *p_enc_in, *p_ZxE, *p_ZxD, *p_dec_outs;
    int *p_idxE, *p_idxD;
    cudaGetSymbolAddress((void**)&p_enc_in,   g_enc_in);
    cudaGetSymbolAddress((void**)&p_ZxE,      g_ZxE);
    cudaGetSymbolAddress((void**)&p_ZxD,      g_ZxD);
    cudaGetSymbolAddress((void**)&p_dec_outs, g_dec_outs);
    cudaGetSymbolAddress((void**)&p_idxE,     g_idx_enc);
    cudaGetSymbolAddress((void**)&p_idxD,     g_idx_dec);

    unsigned short *ei_h,*ei_l,*de_h,*de_l,*di_h,*di_l,*do_h,*do_l,*h1_h,*h1_l;
    unsigned short *wxe_h,*wxe_l,*wxd_h,*wxd_l,*wd_h,*wd_l,*w1_h,*w1_l,*w2_h,*w2_l;
    cudaGetSymbolAddress((void**)&ei_h, g_ei_hi);  cudaGetSymbolAddress((void**)&ei_l, g_ei_lo);
    cudaGetSymbolAddress((void**)&de_h, g_de_hi);  cudaGetSymbolAddress((void**)&de_l, g_de_lo);
    cudaGetSymbolAddress((void**)&di_h, g_di_hi);  cudaGetSymbolAddress((void**)&di_l, g_di_lo);
    cudaGetSymbolAddress((void**)&do_h, g_do_hi);  cudaGetSymbolAddress((void**)&do_l, g_do_lo);
    cudaGetSymbolAddress((void**)&h1_h, g_h1_hi);  cudaGetSymbolAddress((void**)&h1_l, g_h1_lo);
    cudaGetSymbolAddress((void**)&wxe_h, g_wxe_hi); cudaGetSymbolAddress((void**)&wxe_l, g_wxe_lo);
    cudaGetSymbolAddress((void**)&wxd_h, g_wxd_hi); cudaGetSymbolAddress((void**)&wxd_l, g_wxd_lo);
    cudaGetSymbolAddress((void**)&wd_h,  g_wd_hi);  cudaGetSymbolAddress((void**)&wd_l,  g_wd_lo);
    cudaGetSymbolAddress((void**)&w1_h,  g_w1_hi);  cudaGetSymbolAddress((void**)&w1_l,  g_w1_lo);
    cudaGetSymbolAddress((void**)&w2_h,  g_w2_hi);  cudaGetSymbolAddress((void**)&w2_l,  g_w2_lo);

    zero_states_kernel<<<(U_ * B_ + 255) / 256, 256>>>();
    build_rowidx_kernel<<<(ROWS_ + 255) / 256, 256>>>(in_inputs,  p_idxE);
    build_rowidx_kernel<<<(ROWS_ + 255) / 256, 256>>>(in_targets, p_idxD);

    // ---- weight transpose+split conversions ----
    convertBT_kernel<<<dim3(G4_/32,  U_/32),  dim3(32,8)>>>(enc_Wx, wxe_h, wxe_l, U_,  G4_);
    convertBT_kernel<<<dim3(G4_/32,  U_/32),  dim3(32,8)>>>(dec_Wx, wxd_h, wxd_l, U_,  G4_);
    convertBT_kernel<<<dim3(U_/32,   G4_/32), dim3(32,8)>>>(dec_Wd, wd_h,  wd_l,  G4_, U_);
    convertBT_kernel<<<dim3(G4_/32,  U_/32),  dim3(32,8)>>>(out_W1, w1_h,  w1_l,  U_,  G4_);
    convertBT_kernel<<<dim3(PATH_/32,G4_/32), dim3(32,8)>>>(out_W2, w2_h,  w2_l,  G4_, PATH_);
    convert_split_kernel<<<2048, 256>>>(dec_embed, de_h, de_l, (long long)PATH_ * 2048 / 4);

    // ---- encoder front ----
    sgemm_encin<<<dim3(U_/128, ROWS_/128), 256>>>(input_embed, p_idxE, enc_Wd, enc_bd, p_enc_in);
    convert_split_kernel<<<2048, 256>>>(p_enc_in, ei_h, ei_l, (long long)ROWS_ * U_ / 4);
    // ZxE = enc_in @ enc_Wx[0]        [8192,2048] K=512, f32 out
    mma_gemm<false,false,0><<<dim3(G4_/128, ROWS_/128), 256>>>(
        ROWS_, G4_, U_, ei_h, ei_l, nullptr, wxe_h, wxe_l, nullptr, p_ZxE, nullptr, nullptr);
    // dec_in = relu(embed(targets) @ dec_Wd + bd)   [8192,512] K=2048, split out
    mma_gemm<true,true,2><<<dim3(U_/128, ROWS_/128), 256>>>(
        ROWS_, U_, G4_, de_h, de_l, p_idxD, wd_h, wd_l, dec_bd, nullptr, di_h, di_l);
    // ZxD = dec_in @ dec_Wx[0]        [8192,2048] K=512, f32 out
    mma_gemm<false,false,0><<<dim3(G4_/128, ROWS_/128), 256>>>(
        ROWS_, G4_, U_, di_h, di_l, nullptr, wxd_h, wxd_l, nullptr, p_ZxD, nullptr, nullptr);

    // ---- recurrence ----
    lstm_persistent<<<NBLK, 256>>>(enc_Wx, enc_Wh, enc_b, dec_Wx, dec_Wh, dec_b,
                                   p_ZxE, p_ZxD, p_dec_outs);

    // ---- output head ----
    convert_split_kernel<<<2048, 256>>>(p_dec_outs, do_h, do_l, (long long)ROWS_ * U_ / 4);
    // H1 = relu(dec_outs @ out_W1 + b1)   [8192,2048] K=512, split out
    mma_gemm<false,true,2><<<dim3(G4_/128, ROWS_/128), 256>>>(
        ROWS_, G4_, U_, do_h, do_l, nullptr, w1_h, w1_l, out_b1, nullptr, h1_h, h1_l);
    // out = relu(H1 @ out_W2 + b2) scattered to [B,T,PATH]   [8192,8192] K=2048
    mma_gemm<false,true,1><<<dim3(PATH_/128, ROWS_/128), 256>>>(
        ROWS_, PATH_, G4_, h1_h, h1_l, nullptr, w2_h, w2_l, out_b2, (float*)d_out, nullptr, nullptr);
}